// round 10
// baseline (speedup 1.0000x reference)
#include <cuda_runtime.h>

// out[b,o,p] = sum_c refine_w[o,c]*x[b,c,p] + refine_b[o]
// (rest of reference graph is dead: x_back == x exactly, _dead unused)
// B=8, C=64, HW=65536, fp32.
//
// R7/R9: FFMA-pipe-bound. Invariant: FFMA work = 55us of pipe time;
// wall = 55/fma%. Small tile (32 acc regs) for 64-reg/4-CTA occupancy +
// transposed [c][o] weights for ~91% FFMA instruction mix.

#define CC     64
#define HW     65536
#define BP     128          // pixels per block
#define NTHR   256          // 8 warps: warp r owns outputs 8r..8r+7; lane j owns pixels 4j..4j+3

__global__ __launch_bounds__(NTHR, 4) void conv1x1_kernel(
    const float* __restrict__ x,
    const float* __restrict__ w,      // [64][64] (o,c)
    const float* __restrict__ bias,   // [64]
    float* __restrict__ out)
{
    __shared__ float sh_x[CC * BP];   // 32 KB  [c][p]
    __shared__ float sh_w[CC * CC];   // 16 KB  [c][o]  (transposed)

    const int t  = threadIdx.x;
    const int b  = blockIdx.y;
    const int p0 = blockIdx.x * BP;
    const size_t xbase = (size_t)b * CC * HW + p0;

    // ---- stage x tile: 64c x 128p = 2048 float4, fully coalesced ----
#pragma unroll
    for (int k = 0; k < 8; k++) {
        int i  = t + k * NTHR;        // [0, 2048)
        int c  = i >> 5;              // 32 float4 per channel row
        int f4 = i & 31;
        float4 v = *(const float4*)(x + xbase + (size_t)c * HW + f4 * 4);
        *(float4*)(sh_x + c * BP + f4 * 4) = v;
    }
    // ---- stage weights transposed: sh_w[c*64+o] = w[o*64+c] (16KB, L2-hot) ----
#pragma unroll
    for (int k = 0; k < 16; k++) {
        int i = t + k * NTHR;         // i = c*64 + o
        int c = i >> 6;
        int o = i & 63;
        sh_w[i] = __ldg(w + o * CC + c);
    }
    __syncthreads();

    const int r = t >> 5;   // warp id: outputs 8r..8r+7
    const int j = t & 31;   // lane: pixels 4j..4j+3

    const float* xp = sh_x + j * 4;
    const float* wp = sh_w + 8 * r;

    float4 acc[8];
#pragma unroll
    for (int m = 0; m < 8; m++) acc[m] = make_float4(0.f, 0.f, 0.f, 0.f);

#define FMA4(A, S, V)                       \
    A.x = fmaf((S), (V).x, A.x);            \
    A.y = fmaf((S), (V).y, A.y);            \
    A.z = fmaf((S), (V).z, A.z);            \
    A.w = fmaf((S), (V).w, A.w);

#pragma unroll 4
    for (int c = 0; c < CC; c++) {
        // 1x LDS.128 x (conflict-free) + 2x LDS.128 w (broadcast) per 32 FFMA
        float4 xv  = *(const float4*)(xp);
        float4 w03 = *(const float4*)(wp);       // outs 8r..8r+3
        float4 w47 = *(const float4*)(wp + 4);   // outs 8r+4..8r+7
        xp += BP;
        wp += CC;

        FMA4(acc[0], w03.x, xv);
        FMA4(acc[1], w03.y, xv);
        FMA4(acc[2], w03.z, xv);
        FMA4(acc[3], w03.w, xv);
        FMA4(acc[4], w47.x, xv);
        FMA4(acc[5], w47.y, xv);
        FMA4(acc[6], w47.z, xv);
        FMA4(acc[7], w47.w, xv);
    }

    // ---- epilogue: + bias, coalesced float4 stores ----
#pragma unroll
    for (int m = 0; m < 8; m++) {
        int o = 8 * r + m;
        float bo = __ldg(bias + o);
        float4 v = acc[m];
        v.x += bo; v.y += bo; v.z += bo; v.w += bo;
        *(float4*)(out + ((size_t)b * CC + o) * HW + p0 + 4 * j) = v;
    }
}

extern "C" void kernel_launch(void* const* d_in, const int* in_sizes, int n_in,
                              void* d_out, int out_size)
{
    (void)in_sizes; (void)n_in; (void)out_size;
    const float* x    = (const float*)d_in[0];   // x
    const float* w    = (const float*)d_in[11];  // refine_w
    const float* bias = (const float*)d_in[12];  // refine_b
    float* out = (float*)d_out;

    dim3 grid(HW / BP, 8);   // 512 pixel tiles x 8 batches
    conv1x1_kernel<<<grid, NTHR>>>(x, w, bias, out);
}